// round 2
// baseline (speedup 1.0000x reference)
#include <cuda_runtime.h>

// Problem: out = x * (1 + softmax(leaky(semantic@W1^T + b1)@W2^T + b2))
// x: [B=8, C=256, H=256, W=256] fp32. Inputs: x, semantic, W1, b1, W2, b2.

#define B 8
#define C 256
#define HW 65536              // 256*256 elements per (b,c) plane
#define HW4 (HW / 4)          // float4 count per plane = 16384

// Scratch for the per-channel gate (1 + softmax weight). Allocation-free rule:
// use a __device__ global.
__device__ float g_gate[B * C];

// ---------------------------------------------------------------------------
// Kernel A: compute gate[b, c] = 1 + softmax_c(MLP(semantic[b]))
// One block per batch (8 blocks), 256 threads (one per channel).
// ---------------------------------------------------------------------------
__global__ void gate_kernel(const float* __restrict__ semantic,
                            const float* __restrict__ W1,
                            const float* __restrict__ b1,
                            const float* __restrict__ W2,
                            const float* __restrict__ b2) {
    __shared__ float sem[C];
    __shared__ float hbuf[C];
    __shared__ float red[32];

    const int b = blockIdx.x;
    const int t = threadIdx.x;       // 0..255
    const int lane = t & 31;
    const int warp = t >> 5;

    // load semantic row
    sem[t] = semantic[b * C + t];
    __syncthreads();

    // h[t] = b1[t] + sum_k sem[k] * W1[t, k];  LeakyReLU(0.1)
    float h = b1[t];
    const float* w1row = W1 + t * C;
    #pragma unroll 8
    for (int k = 0; k < C; k++) h += sem[k] * w1row[k];
    h = (h > 0.f) ? h : 0.1f * h;
    hbuf[t] = h;
    __syncthreads();

    // logits[t] = b2[t] + sum_j hbuf[j] * W2[t, j]
    float logit = b2[t];
    const float* w2row = W2 + t * C;
    #pragma unroll 8
    for (int j = 0; j < C; j++) logit += hbuf[j] * w2row[j];

    // block-wide softmax over 256 values
    // max reduce
    float m = logit;
    #pragma unroll
    for (int o = 16; o > 0; o >>= 1)
        m = fmaxf(m, __shfl_xor_sync(0xFFFFFFFFu, m, o));
    if (lane == 0) red[warp] = m;
    __syncthreads();
    if (warp == 0) {
        float v = (lane < 8) ? red[lane] : -3.4e38f;
        #pragma unroll
        for (int o = 16; o > 0; o >>= 1)
            v = fmaxf(v, __shfl_xor_sync(0xFFFFFFFFu, v, o));
        if (lane == 0) red[0] = v;
    }
    __syncthreads();
    const float gmax = red[0];
    __syncthreads();

    float e = __expf(logit - gmax);

    // sum reduce
    float s = e;
    #pragma unroll
    for (int o = 16; o > 0; o >>= 1)
        s += __shfl_xor_sync(0xFFFFFFFFu, s, o);
    if (lane == 0) red[warp] = s;
    __syncthreads();
    if (warp == 0) {
        float v = (lane < 8) ? red[lane] : 0.f;
        #pragma unroll
        for (int o = 16; o > 0; o >>= 1)
            v += __shfl_xor_sync(0xFFFFFFFFu, v, o);
        if (lane == 0) red[0] = v;
    }
    __syncthreads();
    const float gsum = red[0];

    g_gate[b * C + t] = 1.f + e / gsum;
}

// ---------------------------------------------------------------------------
// Kernel B: out = x * gate[plane], one block per (b,c) plane.
// 65536 floats per plane = 16384 float4; 256 threads x 64 iterations.
// Pure HBM streaming, fully coalesced.
// ---------------------------------------------------------------------------
__global__ __launch_bounds__(256)
void scale_kernel(const float4* __restrict__ x, float4* __restrict__ out) {
    const int plane = blockIdx.x;              // = b*C + c
    const float s = g_gate[plane];
    const float4* xin = x + (size_t)plane * HW4;
    float4*       xo  = out + (size_t)plane * HW4;

    #pragma unroll 8
    for (int i = threadIdx.x; i < HW4; i += 256) {
        float4 v = xin[i];
        v.x *= s; v.y *= s; v.z *= s; v.w *= s;
        xo[i] = v;
    }
}

extern "C" void kernel_launch(void* const* d_in, const int* in_sizes, int n_in,
                              void* d_out, int out_size) {
    const float* x        = (const float*)d_in[0];
    const float* semantic = (const float*)d_in[1];
    const float* W1       = (const float*)d_in[2];
    const float* b1       = (const float*)d_in[3];
    const float* W2       = (const float*)d_in[4];
    const float* b2       = (const float*)d_in[5];
    float* out = (float*)d_out;

    gate_kernel<<<B, C>>>(semantic, W1, b1, W2, b2);
    scale_kernel<<<B * C, 256>>>((const float4*)x, (float4*)out);
}

// round 3
// speedup vs baseline: 1.3406x; 1.3406x over previous
#include <cuda_runtime.h>

// out = x * (1 + softmax(leaky(semantic@W1^T + b1)@W2^T + b2))
// x: [B=8, C=256, H=256, W=256] fp32.

#define B 8
#define C 256
#define HW 65536
#define HW4 (HW / 4)

__device__ float g_gate[B * C];

// ---------------------------------------------------------------------------
// Fused gate kernel: 8 blocks x 1024 threads (32 warps).
// Warp w computes channels [w*8, w*8+8) for each GEMV stage via warp-reduced
// float4 dots. Softmax done by threads 0..255 at the end.
// ---------------------------------------------------------------------------
__global__ __launch_bounds__(1024)
void gate_kernel(const float* __restrict__ semantic,
                 const float* __restrict__ W1,
                 const float* __restrict__ b1,
                 const float* __restrict__ W2,
                 const float* __restrict__ b2) {
    __shared__ float sem[C];
    __shared__ float hbuf[C];
    __shared__ float lbuf[C];
    __shared__ float red[32];

    const int b    = blockIdx.x;
    const int t    = threadIdx.x;      // 0..1023
    const int lane = t & 31;
    const int warp = t >> 5;           // 0..31

    // load semantic row (256 floats) into smem
    if (t < C) sem[t] = semantic[b * C + t];
    __syncthreads();

    const float4* sem4 = (const float4*)sem;
    // each lane covers float4 indices {lane, lane+32} of a 64-float4 row
    const float4 s0 = sem4[lane];
    const float4 s1 = sem4[lane + 32];

    // ---- stage 1: h = leaky(semantic @ W1^T + b1), 8 channels per warp ----
    #pragma unroll
    for (int i = 0; i < 8; i++) {
        const int c = warp * 8 + i;
        const float4* w4 = (const float4*)(W1 + c * C);
        const float4 a0 = w4[lane];
        const float4 a1 = w4[lane + 32];
        float d = a0.x * s0.x + a0.y * s0.y + a0.z * s0.z + a0.w * s0.w
                + a1.x * s1.x + a1.y * s1.y + a1.z * s1.z + a1.w * s1.w;
        #pragma unroll
        for (int o = 16; o > 0; o >>= 1)
            d += __shfl_xor_sync(0xFFFFFFFFu, d, o);
        if (lane == 0) {
            float h = d + b1[c];
            hbuf[c] = (h > 0.f) ? h : 0.1f * h;
        }
    }
    __syncthreads();

    const float4* h4 = (const float4*)hbuf;
    const float4 h0 = h4[lane];
    const float4 h1 = h4[lane + 32];

    // ---- stage 2: logits = h @ W2^T + b2 ----
    #pragma unroll
    for (int i = 0; i < 8; i++) {
        const int c = warp * 8 + i;
        const float4* w4 = (const float4*)(W2 + c * C);
        const float4 a0 = w4[lane];
        const float4 a1 = w4[lane + 32];
        float d = a0.x * h0.x + a0.y * h0.y + a0.z * h0.z + a0.w * h0.w
                + a1.x * h1.x + a1.y * h1.y + a1.z * h1.z + a1.w * h1.w;
        #pragma unroll
        for (int o = 16; o > 0; o >>= 1)
            d += __shfl_xor_sync(0xFFFFFFFFu, d, o);
        if (lane == 0) lbuf[c] = d + b2[c];
    }
    __syncthreads();

    // ---- softmax over 256 logits (threads 0..255) + gate write ----
    if (t < C) {
        const float logit = lbuf[t];
        float m = logit;
        #pragma unroll
        for (int o = 16; o > 0; o >>= 1)
            m = fmaxf(m, __shfl_xor_sync(0xFFFFFFFFu, m, o));
        if (lane == 0) red[warp] = m;          // warp 0..7
        __syncthreads();
        if (warp == 0) {
            float v = (lane < 8) ? red[lane] : -3.4e38f;
            #pragma unroll
            for (int o = 16; o > 0; o >>= 1)
                v = fmaxf(v, __shfl_xor_sync(0xFFFFFFFFu, v, o));
            if (lane == 0) red[0] = v;
        }
        __syncthreads();
        const float gmax = red[0];
        __syncthreads();

        const float e = __expf(logit - gmax);
        float s = e;
        #pragma unroll
        for (int o = 16; o > 0; o >>= 1)
            s += __shfl_xor_sync(0xFFFFFFFFu, s, o);
        if (lane == 0) red[warp] = s;
        __syncthreads();
        if (warp == 0) {
            float v = (lane < 8) ? red[lane] : 0.f;
            #pragma unroll
            for (int o = 16; o > 0; o >>= 1)
                v += __shfl_xor_sync(0xFFFFFFFFu, v, o);
            if (lane == 0) red[0] = v;
        }
        __syncthreads();
        g_gate[b * C + t] = 1.f + e / red[0];
    }
}

// ---------------------------------------------------------------------------
// Scale kernel: out = x * gate[plane]; one block per (b,c) plane.
// Already at 82.7% DRAM — leave structure unchanged.
// ---------------------------------------------------------------------------
__global__ __launch_bounds__(256)
void scale_kernel(const float4* __restrict__ x, float4* __restrict__ out) {
    const int plane = blockIdx.x;
    const float s = g_gate[plane];
    const float4* xin = x + (size_t)plane * HW4;
    float4*       xo  = out + (size_t)plane * HW4;

    #pragma unroll 8
    for (int i = threadIdx.x; i < HW4; i += 256) {
        float4 v = xin[i];
        v.x *= s; v.y *= s; v.z *= s; v.w *= s;
        xo[i] = v;
    }
}

extern "C" void kernel_launch(void* const* d_in, const int* in_sizes, int n_in,
                              void* d_out, int out_size) {
    const float* x        = (const float*)d_in[0];
    const float* semantic = (const float*)d_in[1];
    const float* W1       = (const float*)d_in[2];
    const float* b1       = (const float*)d_in[3];
    const float* W2       = (const float*)d_in[4];
    const float* b2       = (const float*)d_in[5];
    float* out = (float*)d_out;

    gate_kernel<<<B, 1024>>>(semantic, W1, b1, W2, b2);
    scale_kernel<<<B * C, 256>>>((const float4*)x, (float4*)out);
}